// round 1
// baseline (speedup 1.0000x reference)
#include <cuda_runtime.h>
#include <cuda_bf16.h>
#include <math.h>

// ---------------- problem constants ----------------
#define Tn     4096      // B*S tokens
#define Sn     2048
#define Bn     2
#define DIMn   2048
#define NHn    16
#define NOPEn  128
#define ROPEn  64
#define QDn    192       // NOPE+ROPE
#define VHn    128
#define KVRn   512
#define NEn    8
#define MINTERn 1408
#define SHIn   2816
#define QPROJ  3072      // NH*QD
#define KVAP   576       // KVR+ROPE
#define KVBP   4096      // NH*(NOPE+VH)
#define MOE_ROWS 9216    // 72 tiles of 128 (worst-case padded 8192 + 8*127)
#define MOE_TILES 72

// ---------------- scratch (device globals; no allocs allowed) ----------------
__device__ float g_nx[Tn*DIMn];
__device__ float g_q[Tn*QPROJ];
__device__ float g_kv[Tn*KVAP];
__device__ float g_ckv[Tn*KVRn];
__device__ float g_kpe[Tn*ROPEn];
__device__ float g_kvb[Tn*KVBP];
__device__ float g_scores[134217728];       // 32 * 2048 * 2048
__device__ float g_attn[Tn*DIMn];
__device__ float g_h[Tn*DIMn];
__device__ float g_nh[Tn*DIMn];
__device__ float g_xg[MOE_ROWS*DIMn];
__device__ float g_t1[MOE_ROWS*MINTERn];
__device__ float g_t3[MOE_ROWS*MINTERn];
__device__ float g_eo[MOE_ROWS*DIMn];
__device__ float g_s1[Tn*SHIn];
__device__ float g_s3[Tn*SHIn];
__device__ float g_sh[Tn*DIMn];
__device__ int   g_counts[NEn];
__device__ int   g_off[NEn+1];
__device__ int   g_tile_expert[MOE_TILES];
__device__ int   g_bucket_ts[NEn*Tn];
__device__ float g_bucket_gate[NEn*Tn];
__device__ int   g_flat_tok[MOE_ROWS];
__device__ int   g_tok2row[Tn*2];
__device__ float g_tok2gate[Tn*2];

// ---------------- generic SGEMM: C = A @ W^T (or A @ B), batched ----------------
// flags: bit0 accumulate (C+=), bit1 causal tile skip, bit2 K-limit by row tile,
//        bit3 W is [K,N] (A@B form; requires N%4==0)
__global__ __launch_bounds__(256) void sgemm_k(
    const float* __restrict__ A, const float* __restrict__ W, float* __restrict__ C,
    int M, int N, int K, int lda, int ldb, int ldc,
    long sA0, long sA1, long sW0, long sW1, long sC0, long sC1, int ZH,
    const int* __restrict__ tileExpert, long wStride, int flags)
{
    int bx = blockIdx.x, by = blockIdx.y, z = blockIdx.z;
    if ((flags & 2) && bx > by) return;               // fully-masked causal tile
    if (tileExpert) { int te = tileExpert[by]; if (te < 0) return; W += (long)te * wStride; }
    int zb = z / ZH, zh = z - zb * ZH;
    A += zb * sA0 + (long)zh * sA1;
    W += zb * sW0 + (long)zh * sW1;
    C += zb * sC0 + (long)zh * sC1;
    int Keff = K;
    if (flags & 4) { int kl = (by + 1) * 128; if (kl < Keff) Keff = kl; }

    __shared__ float As[8][128];
    __shared__ float Bs[8][128];
    int tid = threadIdx.x;
    int ty = tid >> 4, tx = tid & 15;
    float acc[8][8];
#pragma unroll
    for (int i = 0; i < 8; i++)
#pragma unroll
        for (int j = 0; j < 8; j++) acc[i][j] = 0.f;

    int arow = tid >> 1;
    int ak   = (tid & 1) * 4;
    const float* Ap = A + (long)(by * 128 + arow) * lda + ak;
    bool aval = (by * 128 + arow) < M;

    bool transB = (flags & 8) != 0;
    int wrow = tid >> 1;
    int wk   = (tid & 1) * 4;
    const float* Wp1 = W + (long)(bx * 128 + wrow) * ldb + wk;
    bool wval1 = (bx * 128 + wrow) < N;
    int bkr = tid >> 5;
    int bcc = (tid & 31) * 4;
    const float* Wp2 = W + (long)bkr * ldb + bx * 128 + bcc;
    bool wval2 = (bx * 128 + bcc) < N;

    for (int k0 = 0; k0 < Keff; k0 += 8) {
        float4 fa = make_float4(0.f, 0.f, 0.f, 0.f);
        if (aval) fa = *(const float4*)(Ap + k0);
        As[ak+0][arow] = fa.x; As[ak+1][arow] = fa.y;
        As[ak+2][arow] = fa.z; As[ak+3][arow] = fa.w;
        if (!transB) {
            float4 fw = make_float4(0.f, 0.f, 0.f, 0.f);
            if (wval1) fw = *(const float4*)(Wp1 + k0);
            Bs[wk+0][wrow] = fw.x; Bs[wk+1][wrow] = fw.y;
            Bs[wk+2][wrow] = fw.z; Bs[wk+3][wrow] = fw.w;
        } else {
            float4 fw = make_float4(0.f, 0.f, 0.f, 0.f);
            if (wval2) fw = *(const float4*)(Wp2 + (long)k0 * ldb);
            *(float4*)&Bs[bkr][bcc] = fw;
        }
        __syncthreads();
#pragma unroll
        for (int kk = 0; kk < 8; kk++) {
            float4 a0 = *(const float4*)&As[kk][ty * 8];
            float4 a1 = *(const float4*)&As[kk][ty * 8 + 4];
            float4 b0 = *(const float4*)&Bs[kk][tx * 8];
            float4 b1 = *(const float4*)&Bs[kk][tx * 8 + 4];
            float ra[8] = {a0.x, a0.y, a0.z, a0.w, a1.x, a1.y, a1.z, a1.w};
            float rb[8] = {b0.x, b0.y, b0.z, b0.w, b1.x, b1.y, b1.z, b1.w};
#pragma unroll
            for (int i = 0; i < 8; i++)
#pragma unroll
                for (int j = 0; j < 8; j++)
                    acc[i][j] = fmaf(ra[i], rb[j], acc[i][j]);
        }
        __syncthreads();
    }

    bool add = (flags & 1) != 0;
#pragma unroll
    for (int i = 0; i < 8; i++) {
        int cr = by * 128 + ty * 8 + i;
        if (cr < M) {
            float* Cr = C + (long)cr * ldc + bx * 128 + tx * 8;
#pragma unroll
            for (int j = 0; j < 8; j++) {
                int cc = bx * 128 + tx * 8 + j;
                if (cc < N) { if (add) Cr[j] += acc[i][j]; else Cr[j] = acc[i][j]; }
            }
        }
    }
}

// ---------------- reductions ----------------
__device__ __forceinline__ float warpSum(float v) {
#pragma unroll
    for (int o = 16; o; o >>= 1) v += __shfl_xor_sync(0xffffffffu, v, o);
    return v;
}
__device__ __forceinline__ float warpMax(float v) {
#pragma unroll
    for (int o = 16; o; o >>= 1) v = fmaxf(v, __shfl_xor_sync(0xffffffffu, v, o));
    return v;
}

// ---------------- rmsnorm ----------------
__global__ void rmsnorm_k(const float* __restrict__ x, const float* __restrict__ w,
                          float* __restrict__ y, int D, int ldx, int ldy)
{
    long t = blockIdx.x;
    const float* xr = x + t * ldx;
    float* yr = y + t * ldy;
    float s = 0.f;
    for (int d = threadIdx.x; d < D; d += blockDim.x) { float v = xr[d]; s += v * v; }
    __shared__ float sh[32];
    __shared__ float bc;
    s = warpSum(s);
    int lane = threadIdx.x & 31, wp = threadIdx.x >> 5;
    if (!lane) sh[wp] = s;
    __syncthreads();
    if (threadIdx.x < 32) {
        float r = (threadIdx.x < (blockDim.x >> 5)) ? sh[threadIdx.x] : 0.f;
        r = warpSum(r);
        if (!threadIdx.x) bc = rsqrtf(r / D + 1e-6f);
    }
    __syncthreads();
    float sc = bc;
    for (int d = threadIdx.x; d < D; d += blockDim.x) yr[d] = xr[d] * sc * w[d];
}

// ---------------- rope on k_pe ----------------
__global__ void rope_kpe_k(const float* __restrict__ kv, const float* __restrict__ fc,
                           const float* __restrict__ fs, float* __restrict__ kpe)
{
    long t = blockIdx.x;
    int j = threadIdx.x;                 // 0..31
    int pos = (int)(t % Sn);
    float x1 = kv[t * KVAP + KVRn + 2 * j];
    float x2 = kv[t * KVAP + KVRn + 2 * j + 1];
    float c = fc[pos * 32 + j], s = fs[pos * 32 + j];
    kpe[t * ROPEn + 2 * j]     = x1 * c - x2 * s;
    kpe[t * ROPEn + 2 * j + 1] = x1 * s + x2 * c;
}

// ---------------- rope + scale on q (in place) ----------------
__global__ void ropescale_q_k(float* __restrict__ q, const float* __restrict__ fc,
                              const float* __restrict__ fs)
{
    long th = blockIdx.x;                // t*16 + h
    int pos = (int)((th >> 4) % Sn);
    float* r = q + th * QDn;
    int i = threadIdx.x;                 // 0..95 (pairs)
    const float sc = 0.07216878364870322f;   // 1/sqrt(192)
    if (i < 64) {
        r[2 * i]     *= sc;
        r[2 * i + 1] *= sc;
    } else {
        int j = i - 64;
        float x1 = r[128 + 2 * j], x2 = r[128 + 2 * j + 1];
        float c = fc[pos * 32 + j], s = fs[pos * 32 + j];
        r[128 + 2 * j]     = (x1 * c - x2 * s) * sc;
        r[128 + 2 * j + 1] = (x1 * s + x2 * c) * sc;
    }
}

// ---------------- causal softmax over score rows ----------------
__global__ void softmax_causal_k(float* __restrict__ scores)
{
    long row = blockIdx.x;               // 32*S rows
    int q = (int)(row % Sn);
    float* p = scores + row * Sn;
    int n = q + 1;
    float m = -3.4e38f;
    for (int k = threadIdx.x; k < n; k += blockDim.x) m = fmaxf(m, p[k]);
    __shared__ float shm[32];
    __shared__ float bc0, bc1;
    m = warpMax(m);
    int lane = threadIdx.x & 31, wp = threadIdx.x >> 5;
    if (!lane) shm[wp] = m;
    __syncthreads();
    if (threadIdx.x < 32) {
        float r = (threadIdx.x < (blockDim.x >> 5)) ? shm[threadIdx.x] : -3.4e38f;
        r = warpMax(r);
        if (!threadIdx.x) bc0 = r;
    }
    __syncthreads();
    m = bc0;
    float sum = 0.f;
    for (int k = threadIdx.x; k < n; k += blockDim.x) {
        float e = expf(p[k] - m);
        p[k] = e;
        sum += e;
    }
    __syncthreads();
    sum = warpSum(sum);
    if (!lane) shm[wp] = sum;
    __syncthreads();
    if (threadIdx.x < 32) {
        float r = (threadIdx.x < (blockDim.x >> 5)) ? shm[threadIdx.x] : 0.f;
        r = warpSum(r);
        if (!threadIdx.x) bc1 = 1.f / r;
    }
    __syncthreads();
    float inv = bc1;
    for (int k = threadIdx.x; k < n; k += blockDim.x) p[k] *= inv;
    for (int k = n + threadIdx.x; k < Sn; k += blockDim.x) p[k] = 0.f;
}

// ---------------- router: logits -> top2 -> buckets ----------------
__global__ void router_k(const float* __restrict__ nh, const float* __restrict__ rw,
                         int* __restrict__ counts, int* __restrict__ bucket_ts,
                         float* __restrict__ bucket_gate)
{
    long t = blockIdx.x;
    int wp = threadIdx.x >> 5, lane = threadIdx.x & 31;
    const float* xr = nh + t * DIMn;
    float s = 0.f;
    for (int d = lane; d < DIMn; d += 32) s += xr[d] * rw[(long)wp * DIMn + d];
    s = warpSum(s);
    __shared__ float logit[NEn];
    if (!lane) logit[wp] = s;
    __syncthreads();
    if (threadIdx.x == 0) {
        float mx = logit[0];
#pragma unroll
        for (int e = 1; e < NEn; e++) mx = fmaxf(mx, logit[e]);
        float p[NEn];
#pragma unroll
        for (int e = 0; e < NEn; e++) p[e] = expf(logit[e] - mx);
        int i0 = 0;
#pragma unroll
        for (int e = 1; e < NEn; e++) if (p[e] > p[i0]) i0 = e;
        int i1 = (i0 == 0) ? 1 : 0;
#pragma unroll
        for (int e = 0; e < NEn; e++) if (e != i0 && p[e] > p[i1]) i1 = e;
        float denom = p[i0] + p[i1];
        float g0 = p[i0] / denom, g1 = p[i1] / denom;
        int pos0 = atomicAdd(&counts[i0], 1);
        bucket_ts[i0 * Tn + pos0] = (int)(t * 2);
        bucket_gate[i0 * Tn + pos0] = g0;
        int pos1 = atomicAdd(&counts[i1], 1);
        bucket_ts[i1 * Tn + pos1] = (int)(t * 2 + 1);
        bucket_gate[i1 * Tn + pos1] = g1;
    }
}

// ---------------- expert offsets + tile->expert map ----------------
__global__ void offsets_k(const int* __restrict__ counts, int* __restrict__ off,
                          int* __restrict__ tile_expert)
{
    for (int tl = 0; tl < MOE_TILES; tl++) tile_expert[tl] = -1;
    int o = 0;
    for (int e = 0; e < NEn; e++) {
        off[e] = o;
        int nt = (counts[e] + 127) >> 7;
        for (int i = 0; i < nt; i++) tile_expert[(o >> 7) + i] = e;
        o += nt * 128;
    }
    off[NEn] = o;
}

// ---------------- compact buckets -> flat rows + inverse map ----------------
__global__ void compact_k(const int* __restrict__ counts, const int* __restrict__ off,
                          const int* __restrict__ bucket_ts, const float* __restrict__ bucket_gate,
                          int* __restrict__ flat_tok, int* __restrict__ tok2row,
                          float* __restrict__ tok2gate)
{
    int e = blockIdx.x;
    int cnt = counts[e], base = off[e];
    for (int i = threadIdx.x; i < cnt; i += blockDim.x) {
        int ts = bucket_ts[e * Tn + i];
        int r = base + i;
        flat_tok[r] = ts >> 1;
        tok2row[ts] = r;
        tok2gate[ts] = bucket_gate[e * Tn + i];
    }
}

// ---------------- gather routed tokens ----------------
__global__ void gather_k(const float* __restrict__ nh, const int* __restrict__ flat_tok,
                         float* __restrict__ xg)
{
    long r = blockIdx.x;
    int t = flat_tok[r];
    float4* dst = (float4*)(xg + r * DIMn);
    if (t < 0) {
        float4 z = make_float4(0.f, 0.f, 0.f, 0.f);
        for (int i = threadIdx.x; i < DIMn / 4; i += blockDim.x) dst[i] = z;
    } else {
        const float4* src = (const float4*)(nh + (long)t * DIMn);
        for (int i = threadIdx.x; i < DIMn / 4; i += blockDim.x) dst[i] = src[i];
    }
}

// ---------------- silu(a)*b -> a ----------------
__global__ void silumul_k(float* __restrict__ a, const float* __restrict__ b, long n)
{
    long i = (long)blockIdx.x * blockDim.x + threadIdx.x;
    if (i < n) {
        float x = a[i];
        float s = x / (1.f + expf(-x));
        a[i] = s * b[i];
    }
}

// ---------------- final combine: out = h + sh + g0*eo[r0] + g1*eo[r1] ----------------
__global__ void combine_k(const float* __restrict__ h, const float* __restrict__ sh,
                          const float* __restrict__ eo, const int* __restrict__ tok2row,
                          const float* __restrict__ tok2gate, float* __restrict__ out)
{
    long t = blockIdx.x;
    int r0 = tok2row[t * 2], r1 = tok2row[t * 2 + 1];
    float g0 = tok2gate[t * 2], g1 = tok2gate[t * 2 + 1];
    const float4* H = (const float4*)(h + t * DIMn);
    const float4* SH = (const float4*)(sh + t * DIMn);
    const float4* E0 = (const float4*)(eo + (long)r0 * DIMn);
    const float4* E1 = (const float4*)(eo + (long)r1 * DIMn);
    float4* O = (float4*)(out + t * DIMn);
    for (int i = threadIdx.x; i < DIMn / 4; i += blockDim.x) {
        float4 a = H[i], b = SH[i], c = E0[i], d = E1[i];
        float4 o;
        o.x = a.x + b.x + g0 * c.x + g1 * d.x;
        o.y = a.y + b.y + g0 * c.y + g1 * d.y;
        o.z = a.z + b.z + g0 * c.z + g1 * d.z;
        o.w = a.w + b.w + g0 * c.w + g1 * d.w;
        O[i] = o;
    }
}

// ---------------- host side ----------------
#define SYM(p, s) do { void* _q = nullptr; cudaGetSymbolAddress(&_q, s); p = (decltype(p))_q; } while (0)

static void launch_sgemm(const float* A, const float* W, float* C,
                         int M, int N, int K, int lda, int ldb, int ldc,
                         long sA0, long sA1, long sW0, long sW1, long sC0, long sC1,
                         int ZH, int Z, const int* tileExpert, long wStride, int flags)
{
    dim3 grid((N + 127) / 128, (M + 127) / 128, Z);
    sgemm_k<<<grid, 256>>>(A, W, C, M, N, K, lda, ldb, ldc,
                           sA0, sA1, sW0, sW1, sC0, sC1, ZH, tileExpert, wStride, flags);
}

extern "C" void kernel_launch(void* const* d_in, const int* in_sizes, int n_in,
                              void* d_out, int out_size)
{
    const float* x       = (const float*)d_in[0];
    const float* fcos    = (const float*)d_in[1];
    const float* fsin    = (const float*)d_in[2];
    const float* attn_w  = (const float*)d_in[3];
    const float* wq      = (const float*)d_in[4];
    const float* wkv_a   = (const float*)d_in[5];
    const float* kv_w    = (const float*)d_in[6];
    const float* wkv_b   = (const float*)d_in[7];
    const float* wo      = (const float*)d_in[8];
    const float* ffn_w   = (const float*)d_in[9];
    const float* rw      = (const float*)d_in[10];
    const float* e_w1    = (const float*)d_in[11];
    const float* e_w3    = (const float*)d_in[12];
    const float* e_w2    = (const float*)d_in[13];
    const float* s_w1    = (const float*)d_in[14];
    const float* s_w3    = (const float*)d_in[15];
    const float* s_w2    = (const float*)d_in[16];
    float* out = (float*)d_out;

    float *nx, *q, *kv, *ckv, *kpe, *kvb, *scores, *attn, *h, *nh;
    float *xg, *t1, *t3, *eo, *s1, *s3, *sh;
    int *counts, *off, *tile_expert, *bucket_ts, *flat_tok, *tok2row;
    float *bucket_gate, *tok2gate;
    SYM(nx, g_nx); SYM(q, g_q); SYM(kv, g_kv); SYM(ckv, g_ckv); SYM(kpe, g_kpe);
    SYM(kvb, g_kvb); SYM(scores, g_scores); SYM(attn, g_attn); SYM(h, g_h); SYM(nh, g_nh);
    SYM(xg, g_xg); SYM(t1, g_t1); SYM(t3, g_t3); SYM(eo, g_eo);
    SYM(s1, g_s1); SYM(s3, g_s3); SYM(sh, g_sh);
    SYM(counts, g_counts); SYM(off, g_off); SYM(tile_expert, g_tile_expert);
    SYM(bucket_ts, g_bucket_ts); SYM(bucket_gate, g_bucket_gate);
    SYM(flat_tok, g_flat_tok); SYM(tok2row, g_tok2row); SYM(tok2gate, g_tok2gate);

    const long SS = (long)Sn * Sn;

    // 1. attention-input rmsnorm
    rmsnorm_k<<<Tn, 256>>>(x, attn_w, nx, DIMn, DIMn, DIMn);
    // 2. q projection
    launch_sgemm(nx, wq, q, Tn, QPROJ, DIMn, DIMn, DIMn, QPROJ,
                 0, 0, 0, 0, 0, 0, 1, 1, nullptr, 0, 0);
    // 3. kv_a projection
    launch_sgemm(nx, wkv_a, kv, Tn, KVAP, DIMn, DIMn, DIMn, KVAP,
                 0, 0, 0, 0, 0, 0, 1, 1, nullptr, 0, 0);
    // 4. c_kv rmsnorm
    rmsnorm_k<<<Tn, 256>>>(kv, kv_w, ckv, KVRn, KVAP, KVRn);
    // 5. rope k_pe
    rope_kpe_k<<<Tn, 32>>>(kv, fcos, fsin, kpe);
    // 6. kv_b projection
    launch_sgemm(ckv, wkv_b, kvb, Tn, KVBP, KVRn, KVRn, KVRn, KVBP,
                 0, 0, 0, 0, 0, 0, 1, 1, nullptr, 0, 0);
    // 7. rope + scale q (in place)
    ropescale_q_k<<<Tn * NHn, 96>>>(q, fcos, fsin);
    // 8. scores = q_nope @ k_nope^T   (batched over 32 (b,h); causal tile skip)
    launch_sgemm(q, kvb, scores, Sn, Sn, NOPEn, QPROJ, KVBP, Sn,
                 (long)Sn * QPROJ, QDn, (long)Sn * KVBP, 256, 16 * SS, SS,
                 16, 32, nullptr, 0, 2);
    // 9. scores += q_pe @ k_pe^T  (k_pe shared across heads)
    launch_sgemm(q + NOPEn, kpe, scores, Sn, Sn, ROPEn, QPROJ, ROPEn, Sn,
                 (long)Sn * QPROJ, QDn, (long)Sn * ROPEn, 0, 16 * SS, SS,
                 16, 32, nullptr, 0, 1 | 2);
    // 10. causal softmax
    softmax_causal_k<<<32 * Sn, 256>>>(scores);
    // 11. attn = P @ V  (transB form, K-limited by causal row tile)
    launch_sgemm(scores, kvb + NOPEn, attn, Sn, VHn, Sn, Sn, KVBP, DIMn,
                 16 * SS, SS, (long)Sn * KVBP, 256, (long)Sn * DIMn, VHn,
                 16, 32, nullptr, 0, 4 | 8);
    // 12. h = x + attn @ wo^T
    cudaMemcpyAsync(h, x, (size_t)Tn * DIMn * sizeof(float), cudaMemcpyDeviceToDevice, 0);
    launch_sgemm(attn, wo, h, Tn, DIMn, DIMn, DIMn, DIMn, DIMn,
                 0, 0, 0, 0, 0, 0, 1, 1, nullptr, 0, 1);
    // 13. ffn rmsnorm
    rmsnorm_k<<<Tn, 256>>>(h, ffn_w, nh, DIMn, DIMn, DIMn);
    // 14. routing
    cudaMemsetAsync(counts, 0, NEn * sizeof(int), 0);
    cudaMemsetAsync(flat_tok, 0xFF, MOE_ROWS * sizeof(int), 0);
    router_k<<<Tn, 256>>>(nh, rw, counts, bucket_ts, bucket_gate);
    offsets_k<<<1, 1>>>(counts, off, tile_expert);
    compact_k<<<NEn, 256>>>(counts, off, bucket_ts, bucket_gate, flat_tok, tok2row, tok2gate);
    gather_k<<<MOE_ROWS, 256>>>(nh, flat_tok, xg);
    // 15. expert FFN (grouped GEMM via tile->expert indirection)
    launch_sgemm(xg, e_w1, t1, MOE_ROWS, MINTERn, DIMn, DIMn, DIMn, MINTERn,
                 0, 0, 0, 0, 0, 0, 1, 1, tile_expert, (long)MINTERn * DIMn, 0);
    launch_sgemm(xg, e_w3, t3, MOE_ROWS, MINTERn, DIMn, DIMn, DIMn, MINTERn,
                 0, 0, 0, 0, 0, 0, 1, 1, tile_expert, (long)MINTERn * DIMn, 0);
    {
        long n = (long)MOE_ROWS * MINTERn;
        silumul_k<<<(int)((n + 255) / 256), 256>>>(t1, t3, n);
    }
    launch_sgemm(t1, e_w2, eo, MOE_ROWS, DIMn, MINTERn, MINTERn, MINTERn, DIMn,
                 0, 0, 0, 0, 0, 0, 1, 1, tile_expert, (long)DIMn * MINTERn, 0);
    // 16. shared FFN
    launch_sgemm(nh, s_w1, s1, Tn, SHIn, DIMn, DIMn, DIMn, SHIn,
                 0, 0, 0, 0, 0, 0, 1, 1, nullptr, 0, 0);
    launch_sgemm(nh, s_w3, s3, Tn, SHIn, DIMn, DIMn, DIMn, SHIn,
                 0, 0, 0, 0, 0, 0, 1, 1, nullptr, 0, 0);
    {
        long n = (long)Tn * SHIn;
        silumul_k<<<(int)((n + 255) / 256), 256>>>(s1, s3, n);
    }
    launch_sgemm(s1, s_w2, sh, Tn, DIMn, SHIn, SHIn, SHIn, DIMn,
                 0, 0, 0, 0, 0, 0, 1, 1, nullptr, 0, 0);
    // 17. combine
    combine_k<<<Tn, 256>>>(h, sh, eo, tok2row, tok2gate, out);
}